// round 10
// baseline (speedup 1.0000x reference)
#include <cuda_runtime.h>
#include <cstdint>
#include <cstddef>

#define BB 64
#define TT 512
#define II 128
#define HH 512
#define NCLS 5

typedef unsigned long long u64;
typedef ulonglong2 ull2;

// Scratch — static __device__ arrays per allocation rules.
__device__ float g_xpA[(size_t)BB * TT * HH];   // layer0 xproj
__device__ float g_xpB[(size_t)BB * TT * HH];   // layer1 xproj
__device__ float g_xpC[(size_t)BB * TT * HH];   // layer2 xproj
__device__ float g_ysA[(size_t)BB * TT * HH];   // layer0 hidden states
__device__ float g_ysB[(size_t)BB * TT * HH];   // layer1 hidden states
__device__ float g_hfin[(size_t)BB * HH];       // layer2 final hidden

// Cross-CTA coordination (zeroed by reset_counters before the mega launch).
__device__ int g_jcA;        // A-phase job queue head (1024 jobs)
__device__ int g_jcB0;       // B0 job queue head (1024 jobs)
__device__ int g_jcB1;       // B1 job queue head (1024 jobs)
__device__ int g_dA[4];      // A jobs completed per t-block
__device__ int g_dB[2][4];   // B jobs completed per layer per t-block
__device__ int g_prog[64];   // [layer2][cluster4][rank8] recurrence progress

// ---------------- packed f32x2 helpers ----------------
__device__ __forceinline__ u64 pk2(float x, float y) {
    u64 r; asm("mov.b64 %0, {%1,%2};" : "=l"(r) : "f"(x), "f"(y)); return r;
}
__device__ __forceinline__ float2 upk2(u64 v) {
    float2 f; asm("mov.b64 {%0,%1}, %2;" : "=f"(f.x), "=f"(f.y) : "l"(v)); return f;
}
__device__ __forceinline__ void fma2(u64 &d, u64 a, u64 b) {
    asm("fma.rn.f32x2 %0, %1, %2, %0;" : "+l"(d) : "l"(a), "l"(b));
}

// ---------------- cluster / mbarrier helpers ----------------
__device__ __forceinline__ uint32_t smem_u32(const void* p) {
    uint32_t a;
    asm("{ .reg .u64 t; cvta.to.shared.u64 t, %1; cvt.u32.u64 %0, t; }"
        : "=r"(a) : "l"(p));
    return a;
}
__device__ __forceinline__ uint32_t mapa_u32(uint32_t local, uint32_t rank) {
    uint32_t r;
    asm("mapa.shared::cluster.u32 %0, %1, %2;" : "=r"(r) : "r"(local), "r"(rank));
    return r;
}
__device__ __forceinline__ void mbar_init(uint32_t addr, uint32_t count) {
    asm volatile("mbarrier.init.shared.b64 [%0], %1;" :: "r"(addr), "r"(count) : "memory");
}
__device__ __forceinline__ void mbar_expect_tx(uint32_t addr, uint32_t bytes) {
    asm volatile("mbarrier.arrive.expect_tx.shared.b64 _, [%0], %1;"
                 :: "r"(addr), "r"(bytes) : "memory");
}
__device__ __forceinline__ void bulk_copy_cluster(uint32_t dst_cluster, uint32_t src_cta,
                                                  uint32_t bytes, uint32_t mbar_cluster) {
    asm volatile("cp.async.bulk.shared::cluster.shared::cta.mbarrier::complete_tx::bytes "
                 "[%0], [%1], %2, [%3];"
                 :: "r"(dst_cluster), "r"(src_cta), "r"(bytes), "r"(mbar_cluster) : "memory");
}
__device__ __forceinline__ void mbar_wait_cluster(uint32_t addr, uint32_t parity) {
    asm volatile(
        "{\n\t"
        ".reg .pred P;\n\t"
        "WLP%=:\n\t"
        "mbarrier.try_wait.parity.acquire.cluster.shared::cta.b64 P, [%0], %1, 0x989680;\n\t"
        "@P bra WDN%=;\n\t"
        "bra WLP%=;\n\t"
        "WDN%=:\n\t"
        "}"
        :: "r"(addr), "r"(parity) : "memory");
}
__device__ __forceinline__ void fence_proxy_async_cta() {
    asm volatile("fence.proxy.async.shared::cta;" ::: "memory");
}
__device__ __forceinline__ void cluster_sync_full() {
    asm volatile("barrier.cluster.arrive.aligned;" ::: "memory");
    asm volatile("barrier.cluster.wait.aligned;" ::: "memory");
}

// ---------------- dynamic smem layout ----------------
// rnn view:  HS 64KB | REDV 16KB | OUT 8KB | MBAR 256B   (total 90368)
// gemm view: As2 8KB @0 | Bs2 8KB @8192   (aliases HS; used only pre-init /
//            by worker CTAs / by rnn CTAs after their loop ends)
#define SM_HS    0
#define SM_REDV  65536
#define SM_OUT   81920
#define SM_MBAR  90112
#define SM_TOTAL 90368

// =======================================================================
// One 128x128 GEMM tile: C = A[0:128,0:K] @ W[0:128,0:K]^T + b1 + b2.
// A row stride K, W row stride K, C row stride HH. 256 threads.
// =======================================================================
__device__ __forceinline__ void gemm_tile(
    const float* __restrict__ A, const float* __restrict__ W,
    const float* __restrict__ b1, const float* __restrict__ b2,
    float* __restrict__ C, int K,
    u64 (*As2)[128], u64 (*Bs2)[128])
{
    const int tid = threadIdx.x;
    const int tx = tid & 15;
    const int ty = tid >> 4;
    const int r0  = tid >> 2;
    const int kq0 = tid & 3;

    u64 acc[8][8];
    #pragma unroll
    for (int i = 0; i < 8; i++)
        #pragma unroll
        for (int j = 0; j < 8; j++) acc[i][j] = 0ull;

    const float* pa0 = &A[(size_t)r0        * K + kq0 * 4];
    const float* pa1 = &A[(size_t)(64 + r0) * K + kq0 * 4];
    const float* pw0 = &W[(size_t)r0        * K + kq0 * 4];
    const float* pw1 = &W[(size_t)(64 + r0) * K + kq0 * 4];

    const int ktiles = K >> 4;
    float4 a0 = *(const float4*)pa0;
    float4 a1 = *(const float4*)pa1;
    float4 w0 = *(const float4*)pw0;
    float4 w1 = *(const float4*)pw1;

    for (int kt = 0; kt < ktiles; kt++) {
        __syncthreads();
        As2[kq0 * 2][r0]          = pk2(a0.x, a0.y);
        As2[kq0 * 2 + 1][r0]      = pk2(a0.z, a0.w);
        As2[kq0 * 2][64 + r0]     = pk2(a1.x, a1.y);
        As2[kq0 * 2 + 1][64 + r0] = pk2(a1.z, a1.w);
        Bs2[kq0 * 2][r0]          = pk2(w0.x, w0.y);
        Bs2[kq0 * 2 + 1][r0]      = pk2(w0.z, w0.w);
        Bs2[kq0 * 2][64 + r0]     = pk2(w1.x, w1.y);
        Bs2[kq0 * 2 + 1][64 + r0] = pk2(w1.z, w1.w);
        __syncthreads();

        if (kt + 1 < ktiles) {
            const int kb = (kt + 1) * 16;
            a0 = *(const float4*)(pa0 + kb);
            a1 = *(const float4*)(pa1 + kb);
            w0 = *(const float4*)(pw0 + kb);
            w1 = *(const float4*)(pw1 + kb);
        }

        #pragma unroll
        for (int k2 = 0; k2 < 8; k2++) {
            u64 af[8], bf[8];
            #pragma unroll
            for (int i = 0; i < 8; i++) af[i] = As2[k2][ty + 16 * i];
            #pragma unroll
            for (int j = 0; j < 8; j++) bf[j] = Bs2[k2][tx + 16 * j];
            #pragma unroll
            for (int i = 0; i < 8; i++)
                #pragma unroll
                for (int j = 0; j < 8; j++)
                    fma2(acc[i][j], af[i], bf[j]);
        }
    }

    float bias8[8];
    #pragma unroll
    for (int j = 0; j < 8; j++) {
        int n = tx + 16 * j;
        bias8[j] = b1[n] + b2[n];
    }
    #pragma unroll
    for (int i = 0; i < 8; i++) {
        const size_t m = (size_t)(ty + 16 * i);
        #pragma unroll
        for (int j = 0; j < 8; j++) {
            float2 p = upk2(acc[i][j]);
            C[m * HH + tx + 16 * j] = p.x + p.y + bias8[j];
        }
    }
}

// all 32 prog entries of layer L >= thr ?
__device__ __forceinline__ bool prog_all_ge(int L, int thr) {
    volatile int* p = (volatile int*)&g_prog[L * 32];
    #pragma unroll 4
    for (int q = 0; q < 32; q++)
        if (p[q] < thr) return false;
    return true;
}

// Greedy two-queue B-phase worker. Claims a queue head only when its
// coarse progress gate is already open -> no head-of-line blocking.
__device__ void worker_B(
    const float* __restrict__ ysA, const float* __restrict__ ysB,
    const float* __restrict__ Wih1, const float* __restrict__ bi1,
    const float* __restrict__ bh1,
    const float* __restrict__ Wih2, const float* __restrict__ bi2,
    const float* __restrict__ bh2,
    float* __restrict__ xpB, float* __restrict__ xpC,
    u64 (*As2)[128], u64 (*Bs2)[128])
{
    __shared__ int s_sel, s_idx;
    const int tid = threadIdx.x;
    for (;;) {
        if (tid == 0) {
            int sel = -1, idx = -1;
            for (;;) {
                int h0 = *(volatile int*)&g_jcB0;
                if (h0 < 1024 && prog_all_ge(0, ((h0 >> 8) + 1) * 128)) {
                    idx = atomicAdd(&g_jcB0, 1);
                    if (idx < 1024) { sel = 0; break; }
                }
                int h1 = *(volatile int*)&g_jcB1;
                if (h1 < 1024 && prog_all_ge(1, ((h1 >> 8) + 1) * 128)) {
                    idx = atomicAdd(&g_jcB1, 1);
                    if (idx < 1024) { sel = 1; break; }
                }
                if (*(volatile int*)&g_jcB0 >= 1024 &&
                    *(volatile int*)&g_jcB1 >= 1024) { sel = -2; break; }
                __nanosleep(256);
            }
            s_sel = sel; s_idx = idx;
        }
        __syncthreads();
        const int sel = s_sel, idx = s_idx;
        if (sel == -2) break;
        const int TB = idx >> 8, jj = idx & 255, b = jj >> 2, nt = jj & 3;

        // fine gate: this batch's cluster must have produced ys through TB
        if (tid == 0) {
            volatile int* p = (volatile int*)&g_prog[sel * 32 + (b >> 4) * 8];
            const int thr = TB * 128 + 128;
            for (int q = 0; q < 8; q++)
                while (p[q] < thr) __nanosleep(128);
            __threadfence();
        }
        __syncthreads();

        const float* src = (sel ? ysB : ysA) + (size_t)(b * TT + TB * 128) * HH;
        const float* Wn  = (sel ? Wih2 : Wih1) + (size_t)(nt * 128) * HH;
        const float* b1  = (sel ? bi2 : bi1) + nt * 128;
        const float* b2  = (sel ? bh2 : bh1) + nt * 128;
        float* dst = (sel ? xpC : xpB) + (size_t)(b * TT + TB * 128) * HH + nt * 128;
        gemm_tile(src, Wn, b1, b2, dst, HH, As2, Bs2);
        __syncthreads();
        __threadfence();
        if (tid == 0) atomicAdd(&g_dB[sel][TB], 1);
        __syncthreads();
    }
}

// =======================================================================
// Mega kernel: 18 clusters x 8 CTAs = 144 CTAs, all co-resident.
//   All CTAs first drain the A queue (layer-0 xproj from x, K=128).
//   Clusters 0..3: layer-0 recurrence (16 batches, 2 groups of 8).
//   Clusters 4..7: layer-1. Clusters 8..11: layer-2 (final h only).
//   Clusters 12..17: greedy B-phase GEMM workers. rnn CTAs join B after.
// =======================================================================
__global__ void __launch_bounds__(256, 1) __cluster_dims__(8, 1, 1)
mega(const float* __restrict__ x,
     const float* __restrict__ Wih0, const float* __restrict__ bi0,
     const float* __restrict__ bh0,
     const float* __restrict__ Whh0, const float* __restrict__ Whh1,
     const float* __restrict__ Whh2,
     const float* __restrict__ Wih1, const float* __restrict__ bi1,
     const float* __restrict__ bh1,
     const float* __restrict__ Wih2, const float* __restrict__ bi2,
     const float* __restrict__ bh2,
     float* __restrict__ xpA, float* __restrict__ xpB, float* __restrict__ xpC,
     float* __restrict__ ysA, float* __restrict__ ysB,
     float* __restrict__ hfin)
{
    extern __shared__ char dsm[];
    u64 (*As2)[128] = (u64(*)[128])(dsm);
    u64 (*Bs2)[128] = (u64(*)[128])(dsm + 8192);

    const int tid = threadIdx.x;
    const int cid = blockIdx.x >> 3;

    // =================== phase 0: everyone drains the A queue ==========
    {
        __shared__ int s_job;
        for (;;) {
            if (tid == 0) s_job = atomicAdd(&g_jcA, 1);
            __syncthreads();
            const int j = s_job;
            if (j >= 1024) break;
            const int tb = j >> 8, r8 = j & 255, b = r8 >> 2, nt = r8 & 3;
            gemm_tile(x + (size_t)(b * TT + tb * 128) * II,
                      Wih0 + (size_t)(nt * 128) * II,
                      bi0 + nt * 128, bh0 + nt * 128,
                      xpA + (size_t)(b * TT + tb * 128) * HH + nt * 128,
                      II, As2, Bs2);
            __syncthreads();
            __threadfence();
            if (tid == 0) atomicAdd(&g_dA[tb], 1);
            __syncthreads();
        }
    }

    if (cid >= 12) {
        // =================== worker role ===================
        worker_B(ysA, ysB, Wih1, bi1, bh1, Wih2, bi2, bh2, xpB, xpC, As2, Bs2);
        return;
    }

    // =================== recurrence role ===================
    const int l     = cid >> 2;          // layer 0..2
    const int cin   = cid & 3;           // cluster-in-layer
    const int r     = blockIdx.x & 7;    // rank
    const int bg    = cin * 16;          // first batch
    const int jbase = r * 64;            // first output col

    const float* Whh = (l == 0) ? Whh0 : (l == 1) ? Whh1 : Whh2;
    const float* xp  = (l == 0) ? xpA  : (l == 1) ? xpB  : xpC;
    float* ys        = (l == 0) ? ysA  : (l == 1) ? ysB  : nullptr;
    volatile int* xgate = (volatile int*)((l == 0) ? g_dA : g_dB[l - 1]);

    const int jp = tid & 31;             // lane
    const int kc = tid >> 5;             // warp id == consumed k-chunk
    const int k0 = kc * 64;

    // W_hh slice in registers, k-pair packed
    u64 w[2][32];
    #pragma unroll
    for (int jj = 0; jj < 2; jj++) {
        const float* wrow = &Whh[(size_t)(jbase + jp + jj * 32) * HH + k0];
        #pragma unroll
        for (int kp = 0; kp < 32; kp++) {
            float2 wv = *(const float2*)&wrow[2 * kp];
            w[jj][kp] = pk2(wv.x, wv.y);
        }
    }

    // zero h buffers (aliases the A-phase GEMM smem — drain completed above)
    {
        float4* hz = (float4*)(dsm + SM_HS);
        for (int i = tid; i < 65536 / 16; i += 256)
            hz[i] = make_float4(0.f, 0.f, 0.f, 0.f);
    }
    const uint32_t mb_base = smem_u32(dsm + SM_MBAR);
    const uint32_t hbase   = smem_u32(dsm + SM_HS);
    const uint32_t obase   = smem_u32(dsm + SM_OUT);
    float* redv = (float*)(dsm + SM_REDV);   // [chunk8][batch8][col64]
    float* outp = (float*)(dsm + SM_OUT);    // [g2][buf2][batch8][col64]
    if (tid < 32) {   // 32 mbars: idx = (g*2+buf)*8 + chunk
        mbar_init(mb_base + (uint32_t)tid * 8u, 1);
        mbar_expect_tx(mb_base + (uint32_t)tid * 8u, 2048u);
    }
    __syncthreads();
    cluster_sync_full();

    uint32_t my_mb[2][2];
    #pragma unroll
    for (int g = 0; g < 2; g++)
        #pragma unroll
        for (int b = 0; b < 2; b++)
            my_mb[g][b] = mb_base + (uint32_t)(((g * 2 + b) * 8 + kc)) * 8u;
    int par[2][2] = {{0, 0}, {0, 0}};

    uint32_t dst_q = 0;
    uint32_t rmb[2][2];
    if (tid < 8) {
        const uint32_t q = (uint32_t)tid;
        dst_q = mapa_u32(hbase, q) + (uint32_t)r * 2048u;
        #pragma unroll
        for (int g = 0; g < 2; g++)
            #pragma unroll
            for (int b = 0; b < 2; b++)
                rmb[g][b] = mapa_u32(mb_base + (uint32_t)(((g * 2 + b) * 8 + r)) * 8u, q);
    }

    // reduce mapping: thread -> (cb, cb+4) x col cj, per group
    const int cb = tid >> 6;             // 0..3
    const int cj = tid & 63;
    const float* xp_p[2][2];
    float*       ys_p[2][2];
    #pragma unroll
    for (int g = 0; g < 2; g++)
        #pragma unroll
        for (int h = 0; h < 2; h++) {
            const int batch = bg + g * 8 + cb + h * 4;
            xp_p[g][h] = &xp[((size_t)batch * TT) * HH + jbase + cj];
            if (l < 2) ys_p[g][h] = &ys[((size_t)batch * TT) * HH + jbase + cj];
            else       ys_p[g][h] = nullptr;
        }

    for (int t = 0; t < TT; t++) {
        const int os   = t & 1;
        const int wbuf = os ^ 1;

        // xp availability gate every 128 steps
        if ((t & 127) == 0) {
            if (tid == 0) {
                while (xgate[t >> 7] < 256) __nanosleep(128);
                __threadfence();
            }
            __syncthreads();
        }

        float xpv[2][2];
        #pragma unroll
        for (int g = 0; g < 2; g++) {
            xpv[g][0] = __ldg(xp_p[g][0]);
            xpv[g][1] = __ldg(xp_p[g][1]);
        }

        #pragma unroll
        for (int g = 0; g < 2; g++) {
            // per-warp wait for MY chunk of group g (skip t=0: zeros)
            if (t > 0) {
                mbar_wait_cluster(my_mb[g][os], par[g][os]);
                if (jp == 0) mbar_expect_tx(my_mb[g][os], 2048u);
                par[g][os] ^= 1;
            }

            // partial GEMV: 8 batches, W in regs, h broadcast from smem
            const ull2* hb = (const ull2*)(dsm + SM_HS + g * 32768 + os * 16384
                                           + kc * 2048);
            u64 a0[8], a1[8];
            #pragma unroll
            for (int b = 0; b < 8; b++) { a0[b] = 0ull; a1[b] = 0ull; }
            #pragma unroll
            for (int kv = 0; kv < 16; kv++) {
                const u64 w00 = w[0][2 * kv], w01 = w[0][2 * kv + 1];
                const u64 w10 = w[1][2 * kv], w11 = w[1][2 * kv + 1];
                #pragma unroll
                for (int b = 0; b < 8; b++) {
                    ull2 hv = hb[b * 16 + kv];
                    fma2(a0[b], w00, hv.x);
                    fma2(a0[b], w01, hv.y);
                    fma2(a1[b], w10, hv.x);
                    fma2(a1[b], w11, hv.y);
                }
            }
            #pragma unroll
            for (int b = 0; b < 8; b++) {
                float2 p0 = upk2(a0[b]);
                float2 p1 = upk2(a1[b]);
                redv[(kc * 8 + b) * 64 + jp]      = p0.x + p0.y;
                redv[(kc * 8 + b) * 64 + jp + 32] = p1.x + p1.y;
            }
            __syncthreads();

            // reduce 8 chunks + xproj + relu for two batches
            {
                float s0 = xpv[g][0], s1 = xpv[g][1];
                #pragma unroll
                for (int c = 0; c < 8; c++) {
                    s0 += redv[(c * 8 + cb)     * 64 + cj];
                    s1 += redv[(c * 8 + cb + 4) * 64 + cj];
                }
                s0 = fmaxf(s0, 0.f);
                s1 = fmaxf(s1, 0.f);
                const int ob = (g * 2 + os) * 512;
                outp[ob + cb * 64 + cj]       = s0;
                outp[ob + (cb + 4) * 64 + cj] = s1;
                if (l < 2) {
                    *ys_p[g][0] = s0; ys_p[g][0] += HH;
                    *ys_p[g][1] = s1; ys_p[g][1] += HH;
                } else if (t == TT - 1) {
                    hfin[(size_t)(bg + g * 8 + cb)     * HH + jbase + cj] = s0;
                    hfin[(size_t)(bg + g * 8 + cb + 4) * HH + jbase + cj] = s1;
                }
            }
            __syncthreads();

            // async bulk push: 8 threads, 2KB to each peer's next buffer
            if (t + 1 < TT && tid < 8) {
                fence_proxy_async_cta();
                bulk_copy_cluster(dst_q + (uint32_t)g * 32768u + (uint32_t)wbuf * 16384u,
                                  obase + (uint32_t)(g * 2 + os) * 2048u,
                                  2048u, rmb[g][wbuf]);
            }

            xp_p[g][0] += HH;
            xp_p[g][1] += HH;
        }

        // publish recurrence progress (layers 0,1) every 32 steps
        if (l < 2 && (t & 31) == 31 && tid == 0) {
            __threadfence();
            ((volatile int*)g_prog)[l * 32 + cin * 8 + r] = t + 1;
        }
    }

    cluster_sync_full();   // all inbound DSMEM traffic settled

    // join the B job pool to absorb tails (safe: this layer's progress is final)
    worker_B(ysA, ysB, Wih1, bi1, bh1, Wih2, bi2, bh2, xpB, xpC, As2, Bs2);
}

// =======================================================================
__global__ void reset_counters() {
    const int i = threadIdx.x;
    if (i == 0) { g_jcA = 0; g_jcB0 = 0; g_jcB1 = 0; }
    if (i < 4) g_dA[i] = 0;
    if (i < 8) ((int*)g_dB)[i] = 0;
    if (i < 64) g_prog[i] = 0;
}

// =======================================================================
__global__ void proj_kernel(const float* __restrict__ hfin,
                            const float* __restrict__ Wout,
                            const float* __restrict__ bout,
                            float* __restrict__ out)
{
    const int b    = blockIdx.x;
    const int c    = threadIdx.y;
    const int lane = threadIdx.x;
    const float* hrow = &hfin[(size_t)b * HH];
    const float* wrow = &Wout[(size_t)c * HH];
    float s = 0.f;
    for (int k = lane; k < HH; k += 32) s += hrow[k] * wrow[k];
    #pragma unroll
    for (int o = 16; o > 0; o >>= 1) s += __shfl_down_sync(0xffffffffu, s, o);
    if (lane == 0) out[b * NCLS + c] = s + bout[c];
}

// =======================================================================
extern "C" void kernel_launch(void* const* d_in, const int* in_sizes, int n_in,
                              void* d_out, int out_size)
{
    (void)in_sizes; (void)n_in; (void)out_size;
    const float* x    = (const float*)d_in[0];
    const float* Wih[3] = {(const float*)d_in[1], (const float*)d_in[5], (const float*)d_in[9]};
    const float* Whh[3] = {(const float*)d_in[2], (const float*)d_in[6], (const float*)d_in[10]};
    const float* bih[3] = {(const float*)d_in[3], (const float*)d_in[7], (const float*)d_in[11]};
    const float* bhh[3] = {(const float*)d_in[4], (const float*)d_in[8], (const float*)d_in[12]};
    const float* Wout = (const float*)d_in[13];
    const float* bout = (const float*)d_in[14];
    float* out = (float*)d_out;

    float *xpA, *xpB, *xpC, *ysA, *ysB, *hfin;
    cudaGetSymbolAddress((void**)&xpA, g_xpA);
    cudaGetSymbolAddress((void**)&xpB, g_xpB);
    cudaGetSymbolAddress((void**)&xpC, g_xpC);
    cudaGetSymbolAddress((void**)&ysA, g_ysA);
    cudaGetSymbolAddress((void**)&ysB, g_ysB);
    cudaGetSymbolAddress((void**)&hfin, g_hfin);

    cudaFuncSetAttribute(mega, cudaFuncAttributeMaxDynamicSharedMemorySize, SM_TOTAL);

    reset_counters<<<1, 128>>>();
    mega<<<144, 256, SM_TOTAL>>>(x,
                                 Wih[0], bih[0], bhh[0],
                                 Whh[0], Whh[1], Whh[2],
                                 Wih[1], bih[1], bhh[1],
                                 Wih[2], bih[2], bhh[2],
                                 xpA, xpB, xpC, ysA, ysB, hfin);
    proj_kernel<<<64, dim3(32, 5)>>>(hfin, Wout, bout, out);
}

// round 11
// speedup vs baseline: 1.0970x; 1.0970x over previous
#include <cuda_runtime.h>
#include <cstdint>
#include <cstddef>

#define BB 64
#define TT 512
#define II 128
#define HH 512
#define NCLS 5

typedef unsigned long long u64;
typedef ulonglong2 ull2;

// Scratch — static __device__ arrays per allocation rules.
__device__ float g_xpA[(size_t)BB * TT * HH];   // layer0 xproj
__device__ float g_xpB[(size_t)BB * TT * HH];   // layer1 xproj
__device__ float g_xpC[(size_t)BB * TT * HH];   // layer2 xproj
__device__ float g_ysA[(size_t)BB * TT * HH];   // layer0 hidden states
__device__ float g_ysB[(size_t)BB * TT * HH];   // layer1 hidden states
__device__ float g_ysC[(size_t)BB * TT * HH];   // layer2 hidden states

// Cross-CTA coordination (reset before each mega launch).
__device__ int g_jcA;        // A-phase job queue head (1024 jobs)
__device__ int g_jcB;        // B-phase job queue head (1024 jobs)
__device__ int g_dA[4];      // A jobs completed per t-block
__device__ int g_dB[4];      // B jobs completed per t-block
__device__ int g_prog[64];   // recurrence progress per (cluster, rank)

// ---------------- packed f32x2 helpers ----------------
__device__ __forceinline__ u64 pk2(float x, float y) {
    u64 r; asm("mov.b64 %0, {%1,%2};" : "=l"(r) : "f"(x), "f"(y)); return r;
}
__device__ __forceinline__ float2 upk2(u64 v) {
    float2 f; asm("mov.b64 {%0,%1}, %2;" : "=f"(f.x), "=f"(f.y) : "l"(v)); return f;
}
__device__ __forceinline__ void fma2(u64 &d, u64 a, u64 b) {
    asm("fma.rn.f32x2 %0, %1, %2, %0;" : "+l"(d) : "l"(a), "l"(b));
}

// ---------------- cluster / mbarrier helpers ----------------
__device__ __forceinline__ uint32_t smem_u32(const void* p) {
    uint32_t a;
    asm("{ .reg .u64 t; cvta.to.shared.u64 t, %1; cvt.u32.u64 %0, t; }"
        : "=r"(a) : "l"(p));
    return a;
}
__device__ __forceinline__ uint32_t mapa_u32(uint32_t local, uint32_t rank) {
    uint32_t r;
    asm("mapa.shared::cluster.u32 %0, %1, %2;" : "=r"(r) : "r"(local), "r"(rank));
    return r;
}
__device__ __forceinline__ void mbar_init(uint32_t addr, uint32_t count) {
    asm volatile("mbarrier.init.shared.b64 [%0], %1;" :: "r"(addr), "r"(count) : "memory");
}
__device__ __forceinline__ void mbar_expect_tx(uint32_t addr, uint32_t bytes) {
    asm volatile("mbarrier.arrive.expect_tx.shared.b64 _, [%0], %1;"
                 :: "r"(addr), "r"(bytes) : "memory");
}
__device__ __forceinline__ void bulk_copy_cluster(uint32_t dst_cluster, uint32_t src_cta,
                                                  uint32_t bytes, uint32_t mbar_cluster) {
    asm volatile("cp.async.bulk.shared::cluster.shared::cta.mbarrier::complete_tx::bytes "
                 "[%0], [%1], %2, [%3];"
                 :: "r"(dst_cluster), "r"(src_cta), "r"(bytes), "r"(mbar_cluster) : "memory");
}
__device__ __forceinline__ void mbar_wait_cluster(uint32_t addr, uint32_t parity) {
    asm volatile(
        "{\n\t"
        ".reg .pred P;\n\t"
        "WLP%=:\n\t"
        "mbarrier.try_wait.parity.acquire.cluster.shared::cta.b64 P, [%0], %1, 0x989680;\n\t"
        "@P bra WDN%=;\n\t"
        "bra WLP%=;\n\t"
        "WDN%=:\n\t"
        "}"
        :: "r"(addr), "r"(parity) : "memory");
}
__device__ __forceinline__ void fence_proxy_async_cta() {
    asm volatile("fence.proxy.async.shared::cta;" ::: "memory");
}
__device__ __forceinline__ void cluster_sync_full() {
    asm volatile("barrier.cluster.arrive.aligned;" ::: "memory");
    asm volatile("barrier.cluster.wait.aligned;" ::: "memory");
}

// =======================================================================
// One 128x128 GEMM tile: C = A[0:128,0:K] @ W[0:128,0:K]^T + b1 + b2.
// =======================================================================
__device__ __forceinline__ void gemm_tile(
    const float* __restrict__ A, const float* __restrict__ W,
    const float* __restrict__ b1, const float* __restrict__ b2,
    float* __restrict__ C, int K,
    u64 (*As2)[128], u64 (*Bs2)[128])
{
    const int tid = threadIdx.x;
    const int tx = tid & 15;
    const int ty = tid >> 4;
    const int r0  = tid >> 2;
    const int kq0 = tid & 3;

    u64 acc[8][8];
    #pragma unroll
    for (int i = 0; i < 8; i++)
        #pragma unroll
        for (int j = 0; j < 8; j++) acc[i][j] = 0ull;

    const float* pa0 = &A[(size_t)r0        * K + kq0 * 4];
    const float* pa1 = &A[(size_t)(64 + r0) * K + kq0 * 4];
    const float* pw0 = &W[(size_t)r0        * K + kq0 * 4];
    const float* pw1 = &W[(size_t)(64 + r0) * K + kq0 * 4];

    const int ktiles = K >> 4;
    float4 a0 = *(const float4*)pa0;
    float4 a1 = *(const float4*)pa1;
    float4 w0 = *(const float4*)pw0;
    float4 w1 = *(const float4*)pw1;

    for (int kt = 0; kt < ktiles; kt++) {
        __syncthreads();
        As2[kq0 * 2][r0]          = pk2(a0.x, a0.y);
        As2[kq0 * 2 + 1][r0]      = pk2(a0.z, a0.w);
        As2[kq0 * 2][64 + r0]     = pk2(a1.x, a1.y);
        As2[kq0 * 2 + 1][64 + r0] = pk2(a1.z, a1.w);
        Bs2[kq0 * 2][r0]          = pk2(w0.x, w0.y);
        Bs2[kq0 * 2 + 1][r0]      = pk2(w0.z, w0.w);
        Bs2[kq0 * 2][64 + r0]     = pk2(w1.x, w1.y);
        Bs2[kq0 * 2 + 1][64 + r0] = pk2(w1.z, w1.w);
        __syncthreads();

        if (kt + 1 < ktiles) {
            const int kb = (kt + 1) * 16;
            a0 = *(const float4*)(pa0 + kb);
            a1 = *(const float4*)(pa1 + kb);
            w0 = *(const float4*)(pw0 + kb);
            w1 = *(const float4*)(pw1 + kb);
        }

        #pragma unroll
        for (int k2 = 0; k2 < 8; k2++) {
            u64 af[8], bf[8];
            #pragma unroll
            for (int i = 0; i < 8; i++) af[i] = As2[k2][ty + 16 * i];
            #pragma unroll
            for (int j = 0; j < 8; j++) bf[j] = Bs2[k2][tx + 16 * j];
            #pragma unroll
            for (int i = 0; i < 8; i++)
                #pragma unroll
                for (int j = 0; j < 8; j++)
                    fma2(acc[i][j], af[i], bf[j]);
        }
    }

    float bias8[8];
    #pragma unroll
    for (int j = 0; j < 8; j++) {
        int n = tx + 16 * j;
        bias8[j] = b1[n] + b2[n];
    }
    #pragma unroll
    for (int i = 0; i < 8; i++) {
        const size_t m = (size_t)(ty + 16 * i);
        #pragma unroll
        for (int j = 0; j < 8; j++) {
            float2 p = upk2(acc[i][j]);
            C[m * HH + tx + 16 * j] = p.x + p.y + bias8[j];
        }
    }
}

// ---- execute one claimed B job (blocking fine-gate on g_prog) ----
__device__ __forceinline__ void do_B_job(
    int j, const float* ysrc, const float* Wn,
    const float* b1, const float* b2, float* Cdst,
    u64 (*As2)[128], u64 (*Bs2)[128])
{
    const int tb = j >> 8, r8 = j & 255, b = r8 >> 2, nt = r8 & 3;
    if (threadIdx.x == 0) {
        volatile int* p = (volatile int*)&g_prog[(b >> 3) * 8];
        const int thr = tb * 128 + 128;
        for (int q = 0; q < 8; q++)
            while (p[q] < thr) __nanosleep(128);
        __threadfence();
    }
    __syncthreads();
    gemm_tile(ysrc + (size_t)(b * TT + tb * 128) * HH,
              Wn + (size_t)(nt * 128) * HH,
              b1 + nt * 128, b2 + nt * 128,
              Cdst + (size_t)(b * TT + tb * 128) * HH + nt * 128,
              HH, As2, Bs2);
    __syncthreads();
    __threadfence();
    if (threadIdx.x == 0) atomicAdd(&g_dB[tb], 1);
    __syncthreads();
}

// ---- blocking worker: claims jobs until the queue drains ----
__device__ void worker_loop(
    const float* ysrc, const float* Wn, const float* b1, const float* b2,
    float* Cdst, u64 (*As2)[128], u64 (*Bs2)[128])
{
    __shared__ int s_wjob;
    for (;;) {
        if (threadIdx.x == 0) s_wjob = atomicAdd(&g_jcB, 1);
        __syncthreads();
        const int j = s_wjob;
        if (j >= 1024) break;
        do_B_job(j, ysrc, Wn, b1, b2, Cdst, As2, Bs2);
    }
}

// ---- helper: claims only gate-open head jobs, exits when block0 done ----
__device__ void helper_loop(
    const float* ysrc, const float* Wn, const float* b1, const float* b2,
    float* Cdst, u64 (*As2)[128], u64 (*Bs2)[128])
{
    __shared__ int s_hjob;
    for (;;) {
        if (threadIdx.x == 0) {
            int idx = -2;
            for (;;) {
                if (*(volatile int*)&g_dB[0] >= 256) { idx = -2; break; }
                const int h = *(volatile int*)&g_jcB;
                if (h < 1024) {
                    const int tb = h >> 8, b = (h & 255) >> 2;
                    volatile int* p = (volatile int*)&g_prog[(b >> 3) * 8];
                    const int thr = tb * 128 + 128;
                    bool open = true;
                    for (int q = 0; q < 8; q++)
                        if (p[q] < thr) { open = false; break; }
                    if (open) {
                        const int got = atomicAdd(&g_jcB, 1);
                        if (got < 1024) { idx = got; break; }
                    }
                }
                __nanosleep(256);
            }
            s_hjob = idx;
        }
        __syncthreads();
        const int j = s_hjob;
        if (j < 0) break;
        do_B_job(j, ysrc, Wn, b1, b2, Cdst, As2, Bs2);
    }
}

// =======================================================================
// Recurrence (R9-proven): 8-CTA cluster, 8 batches as 2 groups of 4,
// per-(group,buf,chunk) mbarriers, 1KB bulk-engine pushes.
// =======================================================================
__device__ void rnn_run(
    const float* __restrict__ xp, const float* __restrict__ Whh,
    float* __restrict__ ys,
    volatile int* xgate,          // null -> no xp gating
    volatile int* prog_slot,      // null -> no progress publishing
    int bg, int r,
    ull2 (*h_s)[2][8][4][16], float (*redv)[4][64],
    float (*out_s)[2][4][64], u64 (*mbar)[2][8])
{
    const int tid   = threadIdx.x;
    const int jbase = r * 64;
    const int jp = tid & 31;
    const int kc = tid >> 5;
    const int k0 = kc * 64;

    // W_hh slice in registers, k-pair packed
    u64 w[2][32];
    #pragma unroll
    for (int jj = 0; jj < 2; jj++) {
        const float* wrow = &Whh[(size_t)(jbase + jp + jj * 32) * HH + k0];
        #pragma unroll
        for (int kp = 0; kp < 32; kp++) {
            float2 wv = *(const float2*)&wrow[2 * kp];
            w[jj][kp] = pk2(wv.x, wv.y);
        }
    }

    {
        float4* hz = (float4*)h_s;
        for (int i = tid; i < 2 * 2 * 8 * 4 * 16; i += 256)
            hz[i] = make_float4(0.f, 0.f, 0.f, 0.f);
    }
    const uint32_t mb_base = smem_u32(&mbar[0][0][0]);
    const uint32_t hbase   = smem_u32(&h_s[0][0][0][0][0]);
    const uint32_t obase   = smem_u32(&out_s[0][0][0][0]);
    if (tid < 32) {
        mbar_init(mb_base + (uint32_t)tid * 8u, 1);
        mbar_expect_tx(mb_base + (uint32_t)tid * 8u, 1024u);
    }
    __syncthreads();
    cluster_sync_full();

    uint32_t my_mb[2][2];
    #pragma unroll
    for (int g = 0; g < 2; g++)
        #pragma unroll
        for (int b = 0; b < 2; b++)
            my_mb[g][b] = mb_base + (uint32_t)(((g * 2 + b) * 8 + kc)) * 8u;
    int par[2][2] = {{0, 0}, {0, 0}};

    uint32_t dst_q = 0;
    uint32_t rmb[2][2];
    if (tid < 8) {
        const uint32_t q = (uint32_t)tid;
        dst_q = mapa_u32(hbase, q) + (uint32_t)r * 1024u;
        #pragma unroll
        for (int g = 0; g < 2; g++)
            #pragma unroll
            for (int b = 0; b < 2; b++)
                rmb[g][b] = mapa_u32(mb_base + (uint32_t)(((g * 2 + b) * 8 + r)) * 8u, q);
    }

    const int cb = tid >> 6;
    const int cj = tid & 63;
    const float* xp_p[2];
    float*       ys_p[2];
    #pragma unroll
    for (int g = 0; g < 2; g++) {
        xp_p[g] = &xp[((size_t)(bg + g * 4 + cb) * TT) * HH + jbase + cj];
        ys_p[g] = &ys[((size_t)(bg + g * 4 + cb) * TT) * HH + jbase + cj];
    }

    for (int t = 0; t < TT; t++) {
        const int os   = t & 1;
        const int wbuf = os ^ 1;
        const bool push = (t + 1 < TT);

        if (xgate && (t & 127) == 0) {
            if (tid == 0) {
                while (xgate[t >> 7] < 256) __nanosleep(128);
                __threadfence();
            }
            __syncthreads();
        }

        float xpv[2];
        xpv[0] = __ldg(xp_p[0]);
        xpv[1] = __ldg(xp_p[1]);

        #pragma unroll
        for (int g = 0; g < 2; g++) {
            if (t > 0) {
                mbar_wait_cluster(my_mb[g][os], par[g][os]);
                if (jp == 0) mbar_expect_tx(my_mb[g][os], 1024u);
                par[g][os] ^= 1;
            }

            const ull2* hb = &h_s[g][os][kc][0][0];
            u64 acc0[4], acc1[4];
            #pragma unroll
            for (int b = 0; b < 4; b++) {
                u64 a0 = 0ull, a1 = 0ull;
                #pragma unroll
                for (int kv = 0; kv < 16; kv++) {
                    ull2 hv = hb[b * 16 + kv];
                    fma2(a0, w[0][2 * kv],     hv.x);
                    fma2(a0, w[0][2 * kv + 1], hv.y);
                    fma2(a1, w[1][2 * kv],     hv.x);
                    fma2(a1, w[1][2 * kv + 1], hv.y);
                }
                acc0[b] = a0; acc1[b] = a1;
            }

            #pragma unroll
            for (int b = 0; b < 4; b++) {
                float2 p0 = upk2(acc0[b]);
                float2 p1 = upk2(acc1[b]);
                redv[kc][b][jp]      = p0.x + p0.y;
                redv[kc][b][jp + 32] = p1.x + p1.y;
            }
            __syncthreads();

            {
                float s = xpv[g];
                #pragma unroll
                for (int c = 0; c < 8; c++) s += redv[c][cb][cj];
                s = fmaxf(s, 0.f);
                out_s[g][os][cb][cj] = s;
                *ys_p[g] = s;
                ys_p[g] += HH;
            }
            __syncthreads();

            if (push && tid < 8) {
                fence_proxy_async_cta();
                bulk_copy_cluster(dst_q + (uint32_t)g * 16384u + (uint32_t)wbuf * 8192u,
                                  obase + (uint32_t)(g * 2 + os) * 1024u,
                                  1024u, rmb[g][wbuf]);
            }
        }

        if (prog_slot && (t & 31) == 31 && tid == 0) {
            __threadfence();
            *prog_slot = t + 1;
        }

        xp_p[0] += HH;
        xp_p[1] += HH;
    }

    cluster_sync_full();
}

// =======================================================================
// Launch 1: A-phase (xpA from x) drained by all; clusters 0..7 rnn layer0
// (gated on A); clusters 8..17 workers for B (xpB from ysA). rnn joins B.
// =======================================================================
__global__ void __launch_bounds__(256, 1) __cluster_dims__(8, 1, 1)
mega1(const float* __restrict__ x,
      const float* __restrict__ Wih0, const float* __restrict__ bi0,
      const float* __restrict__ bh0,
      const float* __restrict__ Whh0,
      const float* __restrict__ Wih1, const float* __restrict__ bi1,
      const float* __restrict__ bh1,
      float* __restrict__ xpA, float* __restrict__ xpB,
      float* __restrict__ ysA)
{
    __shared__ ull2 h_s[2][2][8][4][16];
    __shared__ float redv[8][4][64];
    __shared__ __align__(16) float out_s[2][2][4][64];
    __shared__ __align__(8) u64 mbar[2][2][8];
    __shared__ u64 As2[8][128];
    __shared__ u64 Bs2[8][128];
    __shared__ int s_ajob;

    const int tid = threadIdx.x;
    const int cid = blockIdx.x >> 3;
    const int r   = blockIdx.x & 7;

    // phase A: everyone drains the layer-0 xproj queue
    for (;;) {
        if (tid == 0) s_ajob = atomicAdd(&g_jcA, 1);
        __syncthreads();
        const int j = s_ajob;
        if (j >= 1024) break;
        const int tb = j >> 8, r8 = j & 255, b = r8 >> 2, nt = r8 & 3;
        gemm_tile(x + (size_t)(b * TT + tb * 128) * II,
                  Wih0 + (size_t)(nt * 128) * II,
                  bi0 + nt * 128, bh0 + nt * 128,
                  xpA + (size_t)(b * TT + tb * 128) * HH + nt * 128,
                  II, As2, Bs2);
        __syncthreads();
        __threadfence();
        if (tid == 0) atomicAdd(&g_dA[tb], 1);
        __syncthreads();
    }

    if (cid >= 8) {
        worker_loop(ysA, Wih1, bi1, bh1, xpB, As2, Bs2);
        return;
    }

    rnn_run(xpA, Whh0, ysA,
            (volatile int*)g_dA, (volatile int*)&g_prog[cid * 8 + r],
            cid * 8, r, h_s, redv, out_s, mbar);

    worker_loop(ysA, Wih1, bi1, bh1, xpB, As2, Bs2);
}

// =======================================================================
// Launch 2 (merged): clusters 0..7 rnn layer1 (xpB ready, no gate; publish
// prog; join B after). Clusters 8..15: help B (xpC from ysB) until block0
// done, then rnn layer2 gated on g_dB. Clusters 16..17: B workers.
// =======================================================================
__global__ void __launch_bounds__(256, 1) __cluster_dims__(8, 1, 1)
mega2(const float* __restrict__ xpB, const float* __restrict__ Whh1,
      float* __restrict__ ysB,
      const float* __restrict__ Wih2, const float* __restrict__ bi2,
      const float* __restrict__ bh2,
      float* __restrict__ xpC, const float* __restrict__ Whh2,
      float* __restrict__ ysC)
{
    __shared__ ull2 h_s[2][2][8][4][16];
    __shared__ float redv[8][4][64];
    __shared__ __align__(16) float out_s[2][2][4][64];
    __shared__ __align__(8) u64 mbar[2][2][8];
    __shared__ u64 As2[8][128];
    __shared__ u64 Bs2[8][128];

    const int cid = blockIdx.x >> 3;
    const int r   = blockIdx.x & 7;

    if (cid >= 16) {
        worker_loop(ysB, Wih2, bi2, bh2, xpC, As2, Bs2);
        return;
    }

    if (cid < 8) {
        rnn_run(xpB, Whh1, ysB,
                nullptr, (volatile int*)&g_prog[cid * 8 + r],
                cid * 8, r, h_s, redv, out_s, mbar);
        worker_loop(ysB, Wih2, bi2, bh2, xpC, As2, Bs2);
        return;
    }

    // clusters 8..15: help B until xpC block0 complete, then layer-2 rnn
    helper_loop(ysB, Wih2, bi2, bh2, xpC, As2, Bs2);
    rnn_run(xpC, Whh2, ysC,
            (volatile int*)g_dB, nullptr,
            (cid - 8) * 8, r, h_s, redv, out_s, mbar);
}

// =======================================================================
__global__ void reset_counters() {
    const int i = threadIdx.x;
    if (i == 0) { g_jcA = 0; g_jcB = 0; }
    if (i < 4) { g_dA[i] = 0; g_dB[i] = 0; }
    if (i < 64) g_prog[i] = 0;
}

// =======================================================================
__global__ void proj_kernel(const float* __restrict__ ys,
                            const float* __restrict__ Wout,
                            const float* __restrict__ bout,
                            float* __restrict__ out)
{
    const int b    = blockIdx.x;
    const int c    = threadIdx.y;
    const int lane = threadIdx.x;
    const float* hrow = &ys[((size_t)b * TT + (TT - 1)) * HH];
    const float* wrow = &Wout[(size_t)c * HH];
    float s = 0.f;
    for (int k = lane; k < HH; k += 32) s += hrow[k] * wrow[k];
    #pragma unroll
    for (int o = 16; o > 0; o >>= 1) s += __shfl_down_sync(0xffffffffu, s, o);
    if (lane == 0) out[b * NCLS + c] = s + bout[c];
}

// =======================================================================
extern "C" void kernel_launch(void* const* d_in, const int* in_sizes, int n_in,
                              void* d_out, int out_size)
{
    (void)in_sizes; (void)n_in; (void)out_size;
    const float* x    = (const float*)d_in[0];
    const float* Wih[3] = {(const float*)d_in[1], (const float*)d_in[5], (const float*)d_in[9]};
    const float* Whh[3] = {(const float*)d_in[2], (const float*)d_in[6], (const float*)d_in[10]};
    const float* bih[3] = {(const float*)d_in[3], (const float*)d_in[7], (const float*)d_in[11]};
    const float* bhh[3] = {(const float*)d_in[4], (const float*)d_in[8], (const float*)d_in[12]};
    const float* Wout = (const float*)d_in[13];
    const float* bout = (const float*)d_in[14];
    float* out = (float*)d_out;

    float *xpA, *xpB, *xpC, *ysA, *ysB, *ysC;
    cudaGetSymbolAddress((void**)&xpA, g_xpA);
    cudaGetSymbolAddress((void**)&xpB, g_xpB);
    cudaGetSymbolAddress((void**)&xpC, g_xpC);
    cudaGetSymbolAddress((void**)&ysA, g_ysA);
    cudaGetSymbolAddress((void**)&ysB, g_ysB);
    cudaGetSymbolAddress((void**)&ysC, g_ysC);

    // Launch 1: A (xpA) + rnn layer0 + B0 workers (xpB from ysA)
    reset_counters<<<1, 64>>>();
    mega1<<<144, 256>>>(x, Wih[0], bih[0], bhh[0],
                        Whh[0],
                        Wih[1], bih[1], bhh[1],
                        xpA, xpB, ysA);

    // Launch 2: rnn layer1 + B1 (xpC from ysB) + rnn layer2 (gated)
    reset_counters<<<1, 64>>>();
    mega2<<<144, 256>>>(xpB, Whh[1], ysB,
                        Wih[2], bih[2], bhh[2],
                        xpC, Whh[2], ysC);

    proj_kernel<<<64, dim3(32, 5)>>>(ysC, Wout, bout, out);
}